// round 15
// baseline (speedup 1.0000x reference)
#include <cuda_runtime.h>
#include <cuda_fp16.h>
#include <cstdint>

#define N_MAX 100000
#define E_MAX 1600000
#define NBLK_SCAN 128   // max scan blocks (n/1024 <= 98)
#define GPB 64          // nodes per gemm block
#define SS_STRIDE 66    // padded row stride for sS (floats)

// ---------------- scratch (static device memory; no allocation) ----------------
__device__ int   g_zbuf[2 * N_MAX + NBLK_SCAN];   // [deg_out | deg_in | blk_flag]
#define P_DEG_OUT (g_zbuf)
#define P_DEG_IN  (g_zbuf + N_MAX)
#define P_FLAG    (g_zbuf + 2 * N_MAX)
__device__ float g_norm_src[N_MAX];
__device__ float g_norm_dst[N_MAX];
__device__ int   g_row_ptr[N_MAX + 1];
__device__ int   g_fill[N_MAX];
__device__ int   g_col[E_MAX + 16];   // small pad so pipelined int4 prefetch never faults
__device__ __half g_a[N_MAX * 64];  // ping: pre-scaled features (fp16)
__device__ __half g_b[N_MAX * 64];  // pong
__device__ float g_s[N_MAX * 64];   // aggregated sums (fp32)
__device__ unsigned char g_mask[2 * N_MAX * 32];  // per layer: byte per col-pair
__device__ int g_blk_sum[NBLK_SCAN];

// ---------------- threefry-2x32 (exact JAX algorithm, partitionable path) ----------------
__device__ __forceinline__ void d_threefry(uint32_t k0, uint32_t k1,
                                           uint32_t x0, uint32_t x1,
                                           uint32_t& y0, uint32_t& y1) {
    uint32_t k2 = k0 ^ k1 ^ 0x1BD11BDAu;
    x0 += k0; x1 += k1;
#define TFR(r) { x0 += x1; x1 = __funnelshift_l(x1, x1, r); x1 ^= x0; }
    TFR(13) TFR(15) TFR(26) TFR(6)
    x0 += k1; x1 += k2 + 1u;
    TFR(17) TFR(29) TFR(16) TFR(24)
    x0 += k2; x1 += k0 + 2u;
    TFR(13) TFR(15) TFR(26) TFR(6)
    x0 += k0; x1 += k1 + 3u;
    TFR(17) TFR(29) TFR(16) TFR(24)
    x0 += k1; x1 += k2 + 4u;
    TFR(13) TFR(15) TFR(26) TFR(6)
    x0 += k2; x1 += k0 + 5u;
#undef TFR
    y0 = x0; y1 = x1;
}

static inline uint32_t h_rotl(uint32_t x, int r) { return (x << r) | (x >> (32 - r)); }
static void h_threefry(uint32_t k0, uint32_t k1, uint32_t x0, uint32_t x1,
                       uint32_t& y0, uint32_t& y1) {
    uint32_t k2 = k0 ^ k1 ^ 0x1BD11BDAu;
    x0 += k0; x1 += k1;
#define TFR(r) { x0 += x1; x1 = h_rotl(x1, r); x1 ^= x0; }
    TFR(13) TFR(15) TFR(26) TFR(6)
    x0 += k1; x1 += k2 + 1u;
    TFR(17) TFR(29) TFR(16) TFR(24)
    x0 += k2; x1 += k0 + 2u;
    TFR(13) TFR(15) TFR(26) TFR(6)
    x0 += k0; x1 += k1 + 3u;
    TFR(17) TFR(29) TFR(16) TFR(24)
    x0 += k1; x1 += k2 + 4u;
    TFR(13) TFR(15) TFR(26) TFR(6)
    x0 += k2; x1 += k0 + 5u;
#undef TFR
    y0 = x0; y1 = x1;
}

// ---------------- degree count + dropout-mask precompute ----------------
// 2 edges per thread (int2 loads). Atomic part is L2-latency-bound (issue ~5%);
// threefry fills the idle issue slots (R11-measured).
__global__ void k_degree_mask(const int* __restrict__ src, const int* __restrict__ dst,
                              int ehalf, int e, int pairs, int maskWords,
                              uint32_t d0k0, uint32_t d0k1,
                              uint32_t d1k0, uint32_t d1k1) {
    int j = blockIdx.x * blockDim.x + threadIdx.x;
    if (j < ehalf) {
        int2 s2 = ((const int2*)src)[j];
        int2 t2 = ((const int2*)dst)[j];
        atomicAdd(&P_DEG_OUT[s2.x], 1);
        atomicAdd(&P_DEG_OUT[s2.y], 1);
        atomicAdd(&P_DEG_IN[t2.x], 1);
        atomicAdd(&P_DEG_IN[t2.y], 1);
    } else if (2 * j < e) {      // odd tail edge
        atomicAdd(&P_DEG_OUT[src[2 * j]], 1);
        atomicAdd(&P_DEG_IN[dst[2 * j]], 1);
    }
    if (j < maskWords) {
        int p0 = 4 * j;
        int layer = (p0 >= pairs);
        uint32_t k0 = layer ? d1k0 : d0k0;
        uint32_t k1 = layer ? d1k1 : d0k1;
        uint32_t plbase = (uint32_t)(p0 - layer * pairs);
        uint32_t word = 0;
#pragma unroll
        for (int q = 0; q < 4; q++) {
            uint32_t idx = 2u * (plbase + q);
            uint32_t y0, y1, z0, z1;
            d_threefry(k0, k1, 0u, idx, y0, y1);
            d_threefry(k0, k1, 0u, idx + 1u, z0, z1);
            uint32_t b = (1u ^ ((y0 ^ y1) >> 31)) | ((1u ^ ((z0 ^ z1) >> 31)) << 1);
            word |= b << (8 * q);
        }
        ((uint32_t*)g_mask)[j] = word;
    }
}

// fused: norms + single-pass exclusive scan (decoupled lookback) -> row_ptr / fill
// + U0 = fp16(norm_src * x)
__global__ void k_scan_norm_scale(const float* __restrict__ x, int n, int e) {
    __shared__ int s[1024];
    __shared__ float snorm[1024];
    __shared__ int s_prefix;
    int b = blockIdx.x, t = threadIdx.x, i = b * 1024 + t;
    int din = (i < n) ? P_DEG_IN[i] : 0;
    float ns = 0.f;
    if (i < n) {
        int a = P_DEG_OUT[i];
        ns = (a > 0) ? rsqrtf((float)a) : 0.f;
        g_norm_src[i] = ns;
        g_norm_dst[i] = (din > 0) ? rsqrtf((float)din) : 0.f;
    }
    snorm[t] = ns;
    s[t] = din;
    __syncthreads();
    for (int off = 1; off < 1024; off <<= 1) {
        int a = (t >= off) ? s[t - off] : 0;
        __syncthreads();
        s[t] += a;
        __syncthreads();
    }
    if (t == 0) {
        s_prefix = 0;
        g_blk_sum[b] = s[1023];
        __threadfence();
        *((volatile int*)&P_FLAG[b]) = 1;
    }
    __syncthreads();
    if (t < b) {
        while (*((volatile int*)&P_FLAG[t]) == 0) {}
        int v = *((volatile int*)&g_blk_sum[t]);
        atomicAdd(&s_prefix, v);
    }
    __syncthreads();
    int excl = s[t] - din + s_prefix;
    if (i < n) { g_row_ptr[i] = excl; g_fill[i] = excl; }
    if (i == 0) g_row_ptr[n] = e;

    const float4* x4 = (const float4*)x;
    int f4base = b * 1024 * 16;
#pragma unroll
    for (int q = 0; q < 16; q++) {
        int idx = f4base + q * 1024 + t;
        if (idx < n * 16) {
            float nv = snorm[(idx >> 4) - b * 1024];
            float4 v = x4[idx];
            __half2 h0 = __floats2half2_rn(v.x * nv, v.y * nv);
            __half2 h1 = __floats2half2_rn(v.z * nv, v.w * nv);
            uint2 pk;
            pk.x = *reinterpret_cast<uint32_t*>(&h0);
            pk.y = *reinterpret_cast<uint32_t*>(&h1);
            ((uint2*)g_a)[idx] = pk;
        }
    }
}

// CSR fill: 2 edges per thread (int2 loads)
__global__ void k_csr(const int* __restrict__ src, const int* __restrict__ dst,
                      int ehalf, int e) {
    int j = blockIdx.x * blockDim.x + threadIdx.x;
    if (j < ehalf) {
        int2 s2 = ((const int2*)src)[j];
        int2 t2 = ((const int2*)dst)[j];
        int p0 = atomicAdd(&g_fill[t2.x], 1);
        g_col[p0] = s2.x;
        int p1 = atomicAdd(&g_fill[t2.y], 1);
        g_col[p1] = s2.y;
    } else if (2 * j < e) {
        int p = atomicAdd(&g_fill[dst[2 * j]], 1);
        g_col[p] = src[2 * j];
    }
}

// ---------------- packed f32x2 helpers ----------------
__device__ __forceinline__ unsigned long long pk2(float x, float y) {
    unsigned long long r;
    asm("mov.b64 %0, {%1,%2};" : "=l"(r) : "f"(x), "f"(y));
    return r;
}
__device__ __forceinline__ void fma2(unsigned long long& d, unsigned long long a, unsigned long long b) {
    asm("fma.rn.f32x2 %0, %1, %2, %0;" : "+l"(d) : "l"(a), "l"(b));
}
__device__ __forceinline__ float2 upk2(unsigned long long v) {
    float2 r;
    asm("mov.b64 {%0,%1}, %2;" : "=f"(r.x), "=f"(r.y) : "l"(v));
    return r;
}

__device__ __forceinline__ void acch(float& ax, float& ay, uint32_t h) {
    __half2 h2 = *reinterpret_cast<__half2*>(&h);
    float2 f = __half22float2(h2);
    ax += f.x; ay += f.y;
}

// ---------------- pure gather: S[v] = sum_{u in N(v)} U[u] (fp16 -> fp32) ------
// one warp per node; lane = col pair. Software-pipelined: next iteration's col
// int4s are loaded BEFORE this iteration's feature loads, so the col->feature
// dependency chain (2x L2 latency) collapses to ~1x per iteration.
__global__ void __launch_bounds__(256) k_agg(const __half* __restrict__ U, int n) {
    int gw = (blockIdx.x * blockDim.x + threadIdx.x) >> 5;
    int lane = threadIdx.x & 31;
    if (gw >= n) return;
    int s = g_row_ptr[gw], e = g_row_ptr[gw + 1];
    const uint32_t* T2 = (const uint32_t*)U;
    float ax0 = 0.f, ay0 = 0.f, ax1 = 0.f, ay1 = 0.f;

    int i = s;
    // head: align to int4 boundary
    for (; i < e && (i & 3); i++)
        acch(ax0, ay0, T2[g_col[i] * 32 + lane]);

    int nfull = (e - i) >> 3;    // number of full 8-edge iterations
    if (nfull > 0) {
        // prologue: cols for iteration 0 (g_col padded => +8 reads are safe)
        int4 c0 = *(const int4*)&g_col[i];
        int4 c1 = *(const int4*)&g_col[i + 4];
        for (int it = 0; it < nfull; it++) {
            // prefetch next iteration's cols before touching features
            int4 n0 = *(const int4*)&g_col[i + 8];
            int4 n1 = *(const int4*)&g_col[i + 12];
            uint32_t v0 = T2[c0.x * 32 + lane];
            uint32_t v1 = T2[c0.y * 32 + lane];
            uint32_t v2 = T2[c0.z * 32 + lane];
            uint32_t v3 = T2[c0.w * 32 + lane];
            uint32_t v4 = T2[c1.x * 32 + lane];
            uint32_t v5 = T2[c1.y * 32 + lane];
            uint32_t v6 = T2[c1.z * 32 + lane];
            uint32_t v7 = T2[c1.w * 32 + lane];
            acch(ax0, ay0, v0); acch(ax1, ay1, v1);
            acch(ax0, ay0, v2); acch(ax1, ay1, v3);
            acch(ax0, ay0, v4); acch(ax1, ay1, v5);
            acch(ax0, ay0, v6); acch(ax1, ay1, v7);
            c0 = n0; c1 = n1;
            i += 8;
        }
    }
    if (i + 4 <= e) {
        int4 c0 = *(const int4*)&g_col[i];
        uint32_t v0 = T2[c0.x * 32 + lane];
        uint32_t v1 = T2[c0.y * 32 + lane];
        uint32_t v2 = T2[c0.z * 32 + lane];
        uint32_t v3 = T2[c0.w * 32 + lane];
        acch(ax0, ay0, v0); acch(ax1, ay1, v1);
        acch(ax0, ay0, v2); acch(ax1, ay1, v3);
        i += 4;
    }
    for (; i < e; i++)
        acch(ax0, ay0, T2[g_col[i] * 32 + lane]);
    ((float2*)g_s)[gw * 32 + lane] = make_float2(ax0 + ax1, ay0 + ay1);
}

// ---------------- GEMM + epilogue: out = epi(norm_dst*(S@W)+b) ----------------
template <int LAYER>
__global__ void __launch_bounds__(256) k_gemm_epi(void* __restrict__ Unext,
                                                  const float* __restrict__ W,
                                                  const float* __restrict__ bias,
                                                  int pairs, int n) {
    __shared__ unsigned long long sW[64 * 32];
    __shared__ float sS[GPB * SS_STRIDE];
    int t = threadIdx.x;
    int base = blockIdx.x * GPB;
    int rid = t >> 4;
    int cid = t & 15;

    const float2* Wv = (const float2*)W;
    float2 wreg[8];
#pragma unroll
    for (int q = 0; q < 8; q++) wreg[q] = Wv[t + q * 256];

    const float4* S4 = (const float4*)g_s;
    float4 sreg[4];
#pragma unroll
    for (int q = 0; q < 4; q++) {
        int li = q * 256 + t;
        int row = li >> 4;
        int node = base + row;
        sreg[q] = (node < n) ? S4[node * 16 + (li & 15)]
                             : make_float4(0.f, 0.f, 0.f, 0.f);
    }

    unsigned char mb[4][2];
    if (LAYER != 2) {
        const unsigned char* mbase = g_mask + LAYER * pairs;
#pragma unroll
        for (int i = 0; i < 4; i++)
#pragma unroll
            for (int j = 0; j < 2; j++)
                mb[i][j] = mbase[(base + rid + 16 * i) * 32 + cid + 16 * j];
    }

#pragma unroll
    for (int q = 0; q < 8; q++) sW[t + q * 256] = pk2(wreg[q].x, wreg[q].y);
#pragma unroll
    for (int q = 0; q < 4; q++) {
        int li = q * 256 + t;
        int row = li >> 4;
        float* p = &sS[row * SS_STRIDE + (li & 15) * 4];
        p[0] = sreg[q].x; p[1] = sreg[q].y; p[2] = sreg[q].z; p[3] = sreg[q].w;
    }
    __syncthreads();

    unsigned long long acc[4][2];
#pragma unroll
    for (int i = 0; i < 4; i++)
#pragma unroll
        for (int j = 0; j < 2; j++) acc[i][j] = 0ull;

#pragma unroll 8
    for (int k = 0; k < 64; k++) {
        unsigned long long a[4], b[2];
#pragma unroll
        for (int i = 0; i < 4; i++) {
            float h = sS[(rid + 16 * i) * SS_STRIDE + k];
            a[i] = pk2(h, h);
        }
#pragma unroll
        for (int j = 0; j < 2; j++) b[j] = sW[k * 32 + cid + 16 * j];
#pragma unroll
        for (int i = 0; i < 4; i++)
#pragma unroll
            for (int j = 0; j < 2; j++) fma2(acc[i][j], a[i], b[j]);
    }

#pragma unroll
    for (int i = 0; i < 4; i++) {
        int node = base + rid + 16 * i;
        if (node < n) {
            float nd = g_norm_dst[node];
            float ns = (LAYER != 2) ? g_norm_src[node] : 0.f;
#pragma unroll
            for (int j = 0; j < 2; j++) {
                int c = cid + 16 * j;
                float2 bb = ((const float2*)bias)[c];
                float2 v = upk2(acc[i][j]);
                float ox = v.x * nd + bb.x;
                float oy = v.y * nd + bb.y;
                if (LAYER != 2) {
                    ox = fmaxf(ox, 0.f);
                    oy = fmaxf(oy, 0.f);
                    ox = (mb[i][j] & 1) ? ox * 2.f * ns : 0.f;
                    oy = (mb[i][j] & 2) ? oy * 2.f * ns : 0.f;
                    ((__half2*)Unext)[node * 32 + c] = __floats2half2_rn(ox, oy);
                } else {
                    ((float2*)Unext)[node * 32 + c] = make_float2(ox, oy);
                }
            }
        }
    }
}

// ---------------- launch ----------------
extern "C" void kernel_launch(void* const* d_in, const int* in_sizes, int n_in,
                              void* d_out, int out_size) {
    const float* x  = (const float*)d_in[0];
    const float* W0 = (const float*)d_in[1];
    const float* b0 = (const float*)d_in[2];
    const float* W1 = (const float*)d_in[3];
    const float* b1 = (const float*)d_in[4];
    const float* W2 = (const float*)d_in[5];
    const float* b2 = (const float*)d_in[6];
    const int*   src = (const int*)d_in[7];
    const int*   dst = (const int*)d_in[8];
    int n = in_sizes[0] / 64;
    int e = in_sizes[7];
    float* out = (float*)d_out;

    int nb = (n + 1023) / 1024;
    int pairs = n * 32;
    int maskWords = (2 * pairs) / 4;
    int ehalf = e / 2;

    uint32_t d0k0, d0k1, d1k0, d1k1;
    h_threefry(0u, 1u, 0u, 0u, d0k0, d0k1);
    h_threefry(0u, 1u, 0u, 1u, d1k0, d1k1);

    __half* gA; cudaGetSymbolAddress((void**)&gA, g_a);
    __half* gB; cudaGetSymbolAddress((void**)&gB, g_b);
    void* pZ; cudaGetSymbolAddress(&pZ, g_zbuf);

    int aB = (n * 32 + 255) / 256;
    int gBk = (n + GPB - 1) / GPB;
    int dWork = ((ehalf + 1) > maskWords) ? (ehalf + 1) : maskWords;

    cudaMemsetAsync(pZ, 0, (size_t)(2 * N_MAX + NBLK_SCAN) * sizeof(int));

    k_degree_mask<<<(dWork + 255) / 256, 256>>>(src, dst, ehalf, e, pairs, maskWords,
                                                d0k0, d0k1, d1k0, d1k1);       // 0
    k_scan_norm_scale<<<nb, 1024>>>(x, n, e);                                  // 1
    k_csr<<<(ehalf + 1 + 255) / 256, 256>>>(src, dst, ehalf, e);               // 2
    k_agg<<<aB, 256>>>(gA, n);                                                 // 3 (profiled)
    k_gemm_epi<0><<<gBk, 256>>>(gB, W0, b0, pairs, n);                         // 4
    k_agg<<<aB, 256>>>(gB, n);                                                 // 5
    k_gemm_epi<1><<<gBk, 256>>>(gA, W1, b1, pairs, n);                         // 6
    k_agg<<<aB, 256>>>(gA, n);                                                 // 7
    k_gemm_epi<2><<<gBk, 256>>>(out, W2, b2, pairs, n);                        // 8
}

// round 16
// speedup vs baseline: 1.1124x; 1.1124x over previous
#include <cuda_runtime.h>
#include <cuda_fp16.h>
#include <cstdint>

#define N_MAX 100000
#define E_MAX 1600000
#define NBLK_SCAN 128   // max scan blocks (n/1024 <= 98)
#define GPB 64          // nodes per gemm block
#define SS_STRIDE 66    // padded row stride for sS (floats)

// ---------------- scratch (static device memory; no allocation) ----------------
__device__ int   g_zbuf[2 * N_MAX + NBLK_SCAN];   // [deg_out | deg_in | blk_flag]
#define P_DEG_OUT (g_zbuf)
#define P_DEG_IN  (g_zbuf + N_MAX)
#define P_FLAG    (g_zbuf + 2 * N_MAX)
__device__ float g_norm_src[N_MAX];
__device__ float g_norm_dst[N_MAX];
__device__ int   g_row_ptr[N_MAX + 1];
__device__ int   g_fill[N_MAX];
__device__ int   g_col[E_MAX + 16];
__device__ __half g_a[N_MAX * 64];  // ping: pre-scaled features (fp16)
__device__ __half g_b[N_MAX * 64];  // pong
__device__ float g_s[N_MAX * 64];   // aggregated sums (fp32)
__device__ unsigned char g_mask[2 * N_MAX * 32];  // per layer: byte per col-pair
__device__ int g_blk_sum[NBLK_SCAN];

// ---------------- threefry-2x32 (exact JAX algorithm, partitionable path) ----------------
__device__ __forceinline__ void d_threefry(uint32_t k0, uint32_t k1,
                                           uint32_t x0, uint32_t x1,
                                           uint32_t& y0, uint32_t& y1) {
    uint32_t k2 = k0 ^ k1 ^ 0x1BD11BDAu;
    x0 += k0; x1 += k1;
#define TFR(r) { x0 += x1; x1 = __funnelshift_l(x1, x1, r); x1 ^= x0; }
    TFR(13) TFR(15) TFR(26) TFR(6)
    x0 += k1; x1 += k2 + 1u;
    TFR(17) TFR(29) TFR(16) TFR(24)
    x0 += k2; x1 += k0 + 2u;
    TFR(13) TFR(15) TFR(26) TFR(6)
    x0 += k0; x1 += k1 + 3u;
    TFR(17) TFR(29) TFR(16) TFR(24)
    x0 += k1; x1 += k2 + 4u;
    TFR(13) TFR(15) TFR(26) TFR(6)
    x0 += k2; x1 += k0 + 5u;
#undef TFR
    y0 = x0; y1 = x1;
}

static inline uint32_t h_rotl(uint32_t x, int r) { return (x << r) | (x >> (32 - r)); }
static void h_threefry(uint32_t k0, uint32_t k1, uint32_t x0, uint32_t x1,
                       uint32_t& y0, uint32_t& y1) {
    uint32_t k2 = k0 ^ k1 ^ 0x1BD11BDAu;
    x0 += k0; x1 += k1;
#define TFR(r) { x0 += x1; x1 = h_rotl(x1, r); x1 ^= x0; }
    TFR(13) TFR(15) TFR(26) TFR(6)
    x0 += k1; x1 += k2 + 1u;
    TFR(17) TFR(29) TFR(16) TFR(24)
    x0 += k2; x1 += k0 + 2u;
    TFR(13) TFR(15) TFR(26) TFR(6)
    x0 += k0; x1 += k1 + 3u;
    TFR(17) TFR(29) TFR(16) TFR(24)
    x0 += k1; x1 += k2 + 4u;
    TFR(13) TFR(15) TFR(26) TFR(6)
    x0 += k2; x1 += k0 + 5u;
#undef TFR
    y0 = x0; y1 = x1;
}

// ---------------- degree count + dropout-mask precompute ----------------
__global__ void k_degree_mask(const int* __restrict__ src, const int* __restrict__ dst,
                              int ehalf, int e, int pairs, int maskWords,
                              uint32_t d0k0, uint32_t d0k1,
                              uint32_t d1k0, uint32_t d1k1) {
    int j = blockIdx.x * blockDim.x + threadIdx.x;
    if (j < ehalf) {
        int2 s2 = ((const int2*)src)[j];
        int2 t2 = ((const int2*)dst)[j];
        atomicAdd(&P_DEG_OUT[s2.x], 1);
        atomicAdd(&P_DEG_OUT[s2.y], 1);
        atomicAdd(&P_DEG_IN[t2.x], 1);
        atomicAdd(&P_DEG_IN[t2.y], 1);
    } else if (2 * j < e) {
        atomicAdd(&P_DEG_OUT[src[2 * j]], 1);
        atomicAdd(&P_DEG_IN[dst[2 * j]], 1);
    }
    if (j < maskWords) {
        int p0 = 4 * j;
        int layer = (p0 >= pairs);
        uint32_t k0 = layer ? d1k0 : d0k0;
        uint32_t k1 = layer ? d1k1 : d0k1;
        uint32_t plbase = (uint32_t)(p0 - layer * pairs);
        uint32_t word = 0;
#pragma unroll
        for (int q = 0; q < 4; q++) {
            uint32_t idx = 2u * (plbase + q);
            uint32_t y0, y1, z0, z1;
            d_threefry(k0, k1, 0u, idx, y0, y1);
            d_threefry(k0, k1, 0u, idx + 1u, z0, z1);
            uint32_t b = (1u ^ ((y0 ^ y1) >> 31)) | ((1u ^ ((z0 ^ z1) >> 31)) << 1);
            word |= b << (8 * q);
        }
        ((uint32_t*)g_mask)[j] = word;
    }
}

// fused: norms + scan (decoupled lookback) + U0 = fp16(norm_src * x)
__global__ void k_scan_norm_scale(const float* __restrict__ x, int n, int e) {
    __shared__ int s[1024];
    __shared__ float snorm[1024];
    __shared__ int s_prefix;
    int b = blockIdx.x, t = threadIdx.x, i = b * 1024 + t;
    int din = (i < n) ? P_DEG_IN[i] : 0;
    float ns = 0.f;
    if (i < n) {
        int a = P_DEG_OUT[i];
        ns = (a > 0) ? rsqrtf((float)a) : 0.f;
        g_norm_src[i] = ns;
        g_norm_dst[i] = (din > 0) ? rsqrtf((float)din) : 0.f;
    }
    snorm[t] = ns;
    s[t] = din;
    __syncthreads();
    for (int off = 1; off < 1024; off <<= 1) {
        int a = (t >= off) ? s[t - off] : 0;
        __syncthreads();
        s[t] += a;
        __syncthreads();
    }
    if (t == 0) {
        s_prefix = 0;
        g_blk_sum[b] = s[1023];
        __threadfence();
        *((volatile int*)&P_FLAG[b]) = 1;
    }
    __syncthreads();
    if (t < b) {
        while (*((volatile int*)&P_FLAG[t]) == 0) {}
        int v = *((volatile int*)&g_blk_sum[t]);
        atomicAdd(&s_prefix, v);
    }
    __syncthreads();
    int excl = s[t] - din + s_prefix;
    if (i < n) { g_row_ptr[i] = excl; g_fill[i] = excl; }
    if (i == 0) g_row_ptr[n] = e;

    const float4* x4 = (const float4*)x;
    int f4base = b * 1024 * 16;
#pragma unroll
    for (int q = 0; q < 16; q++) {
        int idx = f4base + q * 1024 + t;
        if (idx < n * 16) {
            float nv = snorm[(idx >> 4) - b * 1024];
            float4 v = x4[idx];
            __half2 h0 = __floats2half2_rn(v.x * nv, v.y * nv);
            __half2 h1 = __floats2half2_rn(v.z * nv, v.w * nv);
            uint2 pk;
            pk.x = *reinterpret_cast<uint32_t*>(&h0);
            pk.y = *reinterpret_cast<uint32_t*>(&h1);
            ((uint2*)g_a)[idx] = pk;
        }
    }
}

// CSR fill: 2 edges per thread (int2 loads)
__global__ void k_csr(const int* __restrict__ src, const int* __restrict__ dst,
                      int ehalf, int e) {
    int j = blockIdx.x * blockDim.x + threadIdx.x;
    if (j < ehalf) {
        int2 s2 = ((const int2*)src)[j];
        int2 t2 = ((const int2*)dst)[j];
        int p0 = atomicAdd(&g_fill[t2.x], 1);
        g_col[p0] = s2.x;
        int p1 = atomicAdd(&g_fill[t2.y], 1);
        g_col[p1] = s2.y;
    } else if (2 * j < e) {
        int p = atomicAdd(&g_fill[dst[2 * j]], 1);
        g_col[p] = src[2 * j];
    }
}

// ---------------- packed f32x2 helpers ----------------
__device__ __forceinline__ unsigned long long pk2(float x, float y) {
    unsigned long long r;
    asm("mov.b64 %0, {%1,%2};" : "=l"(r) : "f"(x), "f"(y));
    return r;
}
__device__ __forceinline__ void fma2(unsigned long long& d, unsigned long long a, unsigned long long b) {
    asm("fma.rn.f32x2 %0, %1, %2, %0;" : "+l"(d) : "l"(a), "l"(b));
}
__device__ __forceinline__ float2 upk2(unsigned long long v) {
    float2 r;
    asm("mov.b64 {%0,%1}, %2;" : "=f"(r.x), "=f"(r.y) : "l"(v));
    return r;
}

// accumulate one uint2 (= 4 fp16 features) into a float4
__device__ __forceinline__ void accu2(float4& a, uint2 v) {
    __half2 h0 = *reinterpret_cast<__half2*>(&v.x);
    __half2 h1 = *reinterpret_cast<__half2*>(&v.y);
    float2 f0 = __half22float2(h0);
    float2 f1 = __half22float2(h1);
    a.x += f0.x; a.y += f0.y; a.z += f1.x; a.w += f1.y;
}

// ---------------- pure gather: S[v] = sum_{u in N(v)} U[u] (fp16 -> fp32) ------
// HALF-WARP per node: lanes 0-15 -> node 2g, lanes 16-31 -> node 2g+1.
// Each lane owns 4 columns (uint2 = 8B; 16 lanes = full 128B row). Per 4-edge
// chunk per half: 4 broadcast col LDG.32 (one instr serves both halves) +
// 4 feature LDG.64 + cvt/add => ~4 warp-instrs/edge (was ~10). No SHFL:
// each lane's 4 cols are private to its node -> direct float4 store.
__global__ void __launch_bounds__(256) k_agg(const __half* __restrict__ U, int n) {
    int gw = (blockIdx.x * blockDim.x + threadIdx.x) >> 5;
    int lane = threadIdx.x & 31;
    int h = lane >> 4, laneL = lane & 15;
    int node = 2 * gw + h;
    int s = 0, e = 0;
    if (node < n) { s = g_row_ptr[node]; e = g_row_ptr[node + 1]; }
    const uint2* T = (const uint2*)U;   // fp16 row = 16 uint2
    float4 a0 = make_float4(0.f, 0.f, 0.f, 0.f);
    float4 a1 = make_float4(0.f, 0.f, 0.f, 0.f);

    int i = s;
    for (; i + 4 <= e; i += 4) {
        int c0 = g_col[i];
        int c1 = g_col[i + 1];
        int c2 = g_col[i + 2];
        int c3 = g_col[i + 3];
        uint2 v0 = T[c0 * 16 + laneL];
        uint2 v1 = T[c1 * 16 + laneL];
        uint2 v2 = T[c2 * 16 + laneL];
        uint2 v3 = T[c3 * 16 + laneL];
        accu2(a0, v0); accu2(a1, v1);
        accu2(a0, v2); accu2(a1, v3);
    }
    for (; i < e; i++) {
        int c = g_col[i];
        accu2(a0, T[c * 16 + laneL]);
    }
    a0.x += a1.x; a0.y += a1.y; a0.z += a1.z; a0.w += a1.w;
    if (node < n)
        ((float4*)(g_s + node * 64))[laneL] = a0;
}

// ---------------- GEMM + epilogue: out = epi(norm_dst*(S@W)+b) ----------------
template <int LAYER>
__global__ void __launch_bounds__(256) k_gemm_epi(void* __restrict__ Unext,
                                                  const float* __restrict__ W,
                                                  const float* __restrict__ bias,
                                                  int pairs, int n) {
    __shared__ unsigned long long sW[64 * 32];
    __shared__ float sS[GPB * SS_STRIDE];
    int t = threadIdx.x;
    int base = blockIdx.x * GPB;
    int rid = t >> 4;
    int cid = t & 15;

    const float2* Wv = (const float2*)W;
    float2 wreg[8];
#pragma unroll
    for (int q = 0; q < 8; q++) wreg[q] = Wv[t + q * 256];

    const float4* S4 = (const float4*)g_s;
    float4 sreg[4];
#pragma unroll
    for (int q = 0; q < 4; q++) {
        int li = q * 256 + t;
        int row = li >> 4;
        int node = base + row;
        sreg[q] = (node < n) ? S4[node * 16 + (li & 15)]
                             : make_float4(0.f, 0.f, 0.f, 0.f);
    }

    unsigned char mb[4][2];
    if (LAYER != 2) {
        const unsigned char* mbase = g_mask + LAYER * pairs;
#pragma unroll
        for (int i = 0; i < 4; i++)
#pragma unroll
            for (int j = 0; j < 2; j++)
                mb[i][j] = mbase[(base + rid + 16 * i) * 32 + cid + 16 * j];
    }

#pragma unroll
    for (int q = 0; q < 8; q++) sW[t + q * 256] = pk2(wreg[q].x, wreg[q].y);
#pragma unroll
    for (int q = 0; q < 4; q++) {
        int li = q * 256 + t;
        int row = li >> 4;
        float* p = &sS[row * SS_STRIDE + (li & 15) * 4];
        p[0] = sreg[q].x; p[1] = sreg[q].y; p[2] = sreg[q].z; p[3] = sreg[q].w;
    }
    __syncthreads();

    unsigned long long acc[4][2];
#pragma unroll
    for (int i = 0; i < 4; i++)
#pragma unroll
        for (int j = 0; j < 2; j++) acc[i][j] = 0ull;

#pragma unroll 8
    for (int k = 0; k < 64; k++) {
        unsigned long long a[4], b[2];
#pragma unroll
        for (int i = 0; i < 4; i++) {
            float h = sS[(rid + 16 * i) * SS_STRIDE + k];
            a[i] = pk2(h, h);
        }
#pragma unroll
        for (int j = 0; j < 2; j++) b[j] = sW[k * 32 + cid + 16 * j];
#pragma unroll
        for (int i = 0; i < 4; i++)
#pragma unroll
            for (int j = 0; j < 2; j++) fma2(acc[i][j], a[i], b[j]);
    }

#pragma unroll
    for (int i = 0; i < 4; i++) {
        int node = base + rid + 16 * i;
        if (node < n) {
            float nd = g_norm_dst[node];
            float ns = (LAYER != 2) ? g_norm_src[node] : 0.f;
#pragma unroll
            for (int j = 0; j < 2; j++) {
                int c = cid + 16 * j;
                float2 bb = ((const float2*)bias)[c];
                float2 v = upk2(acc[i][j]);
                float ox = v.x * nd + bb.x;
                float oy = v.y * nd + bb.y;
                if (LAYER != 2) {
                    ox = fmaxf(ox, 0.f);
                    oy = fmaxf(oy, 0.f);
                    ox = (mb[i][j] & 1) ? ox * 2.f * ns : 0.f;
                    oy = (mb[i][j] & 2) ? oy * 2.f * ns : 0.f;
                    ((__half2*)Unext)[node * 32 + c] = __floats2half2_rn(ox, oy);
                } else {
                    ((float2*)Unext)[node * 32 + c] = make_float2(ox, oy);
                }
            }
        }
    }
}

// ---------------- launch ----------------
extern "C" void kernel_launch(void* const* d_in, const int* in_sizes, int n_in,
                              void* d_out, int out_size) {
    const float* x  = (const float*)d_in[0];
    const float* W0 = (const float*)d_in[1];
    const float* b0 = (const float*)d_in[2];
    const float* W1 = (const float*)d_in[3];
    const float* b1 = (const float*)d_in[4];
    const float* W2 = (const float*)d_in[5];
    const float* b2 = (const float*)d_in[6];
    const int*   src = (const int*)d_in[7];
    const int*   dst = (const int*)d_in[8];
    int n = in_sizes[0] / 64;
    int e = in_sizes[7];
    float* out = (float*)d_out;

    int nb = (n + 1023) / 1024;
    int pairs = n * 32;
    int maskWords = (2 * pairs) / 4;
    int ehalf = e / 2;

    uint32_t d0k0, d0k1, d1k0, d1k1;
    h_threefry(0u, 1u, 0u, 0u, d0k0, d0k1);
    h_threefry(0u, 1u, 0u, 1u, d1k0, d1k1);

    __half* gA; cudaGetSymbolAddress((void**)&gA, g_a);
    __half* gB; cudaGetSymbolAddress((void**)&gB, g_b);
    void* pZ; cudaGetSymbolAddress(&pZ, g_zbuf);

    int warps = (n + 1) / 2;                 // 2 nodes per warp
    int aB = (warps * 32 + 255) / 256;
    int gBk = (n + GPB - 1) / GPB;
    int dWork = ((ehalf + 1) > maskWords) ? (ehalf + 1) : maskWords;

    cudaMemsetAsync(pZ, 0, (size_t)(2 * N_MAX + NBLK_SCAN) * sizeof(int));

    k_degree_mask<<<(dWork + 255) / 256, 256>>>(src, dst, ehalf, e, pairs, maskWords,
                                                d0k0, d0k1, d1k0, d1k1);       // 0
    k_scan_norm_scale<<<nb, 1024>>>(x, n, e);                                  // 1
    k_csr<<<(ehalf + 1 + 255) / 256, 256>>>(src, dst, ehalf, e);               // 2
    k_agg<<<aB, 256>>>(gA, n);                                                 // 3 (profiled)
    k_gemm_epi<0><<<gBk, 256>>>(gB, W0, b0, pairs, n);                         // 4
    k_agg<<<aB, 256>>>(gB, n);                                                 // 5
    k_gemm_epi<1><<<gBk, 256>>>(gA, W1, b1, pairs, n);                         // 6
    k_agg<<<aB, 256>>>(gA, n);                                                 // 7
    k_gemm_epi<2><<<gBk, 256>>>(out, W2, b2, pairs, n);                        // 8
}

// round 17
// speedup vs baseline: 1.1658x; 1.0481x over previous
#include <cuda_runtime.h>
#include <cuda_fp16.h>
#include <cstdint>

#define N_MAX 100000
#define E_MAX 1600000
#define NBLK_SCAN 128   // max scan blocks (n/1024 <= 98)
#define GPB 64          // nodes per gemm block
#define SS_STRIDE 66    // padded row stride for sS (floats)

// ---------------- scratch (static device memory; no allocation) ----------------
__device__ int   g_zbuf[2 * N_MAX + NBLK_SCAN];   // [deg_out | deg_in | blk_flag]
#define P_DEG_OUT (g_zbuf)
#define P_DEG_IN  (g_zbuf + N_MAX)
#define P_FLAG    (g_zbuf + 2 * N_MAX)
__device__ float g_norm_src[N_MAX];
__device__ float g_norm_dst[N_MAX];
__device__ int   g_row_ptr[N_MAX + 1];
__device__ int   g_fill[N_MAX];
__device__ int   g_col[E_MAX + 16];
__device__ __half g_a[N_MAX * 64];  // ping: pre-scaled features (fp16)
__device__ __half g_b[N_MAX * 64];  // pong
__device__ float g_s[N_MAX * 64];   // aggregated sums (fp32)
__device__ unsigned char g_mask[2 * N_MAX * 32];  // per layer: byte per col-pair
__device__ int g_blk_sum[NBLK_SCAN];

// ---------------- threefry-2x32 (exact JAX algorithm, partitionable path) ----------------
__device__ __forceinline__ void d_threefry(uint32_t k0, uint32_t k1,
                                           uint32_t x0, uint32_t x1,
                                           uint32_t& y0, uint32_t& y1) {
    uint32_t k2 = k0 ^ k1 ^ 0x1BD11BDAu;
    x0 += k0; x1 += k1;
#define TFR(r) { x0 += x1; x1 = __funnelshift_l(x1, x1, r); x1 ^= x0; }
    TFR(13) TFR(15) TFR(26) TFR(6)
    x0 += k1; x1 += k2 + 1u;
    TFR(17) TFR(29) TFR(16) TFR(24)
    x0 += k2; x1 += k0 + 2u;
    TFR(13) TFR(15) TFR(26) TFR(6)
    x0 += k0; x1 += k1 + 3u;
    TFR(17) TFR(29) TFR(16) TFR(24)
    x0 += k1; x1 += k2 + 4u;
    TFR(13) TFR(15) TFR(26) TFR(6)
    x0 += k2; x1 += k0 + 5u;
#undef TFR
    y0 = x0; y1 = x1;
}

static inline uint32_t h_rotl(uint32_t x, int r) { return (x << r) | (x >> (32 - r)); }
static void h_threefry(uint32_t k0, uint32_t k1, uint32_t x0, uint32_t x1,
                       uint32_t& y0, uint32_t& y1) {
    uint32_t k2 = k0 ^ k1 ^ 0x1BD11BDAu;
    x0 += k0; x1 += k1;
#define TFR(r) { x0 += x1; x1 = h_rotl(x1, r); x1 ^= x0; }
    TFR(13) TFR(15) TFR(26) TFR(6)
    x0 += k1; x1 += k2 + 1u;
    TFR(17) TFR(29) TFR(16) TFR(24)
    x0 += k2; x1 += k0 + 2u;
    TFR(13) TFR(15) TFR(26) TFR(6)
    x0 += k0; x1 += k1 + 3u;
    TFR(17) TFR(29) TFR(16) TFR(24)
    x0 += k1; x1 += k2 + 4u;
    TFR(13) TFR(15) TFR(26) TFR(6)
    x0 += k2; x1 += k0 + 5u;
#undef TFR
    y0 = x0; y1 = x1;
}

// ---------------- degree count + dropout-mask precompute ----------------
__global__ void k_degree_mask(const int* __restrict__ src, const int* __restrict__ dst,
                              int ehalf, int e, int pairs, int maskWords,
                              uint32_t d0k0, uint32_t d0k1,
                              uint32_t d1k0, uint32_t d1k1) {
    int j = blockIdx.x * blockDim.x + threadIdx.x;
    if (j < ehalf) {
        int2 s2 = ((const int2*)src)[j];
        int2 t2 = ((const int2*)dst)[j];
        atomicAdd(&P_DEG_OUT[s2.x], 1);
        atomicAdd(&P_DEG_OUT[s2.y], 1);
        atomicAdd(&P_DEG_IN[t2.x], 1);
        atomicAdd(&P_DEG_IN[t2.y], 1);
    } else if (2 * j < e) {
        atomicAdd(&P_DEG_OUT[src[2 * j]], 1);
        atomicAdd(&P_DEG_IN[dst[2 * j]], 1);
    }
    if (j < maskWords) {
        int p0 = 4 * j;
        int layer = (p0 >= pairs);
        uint32_t k0 = layer ? d1k0 : d0k0;
        uint32_t k1 = layer ? d1k1 : d0k1;
        uint32_t plbase = (uint32_t)(p0 - layer * pairs);
        uint32_t word = 0;
#pragma unroll
        for (int q = 0; q < 4; q++) {
            uint32_t idx = 2u * (plbase + q);
            uint32_t y0, y1, z0, z1;
            d_threefry(k0, k1, 0u, idx, y0, y1);
            d_threefry(k0, k1, 0u, idx + 1u, z0, z1);
            uint32_t b = (1u ^ ((y0 ^ y1) >> 31)) | ((1u ^ ((z0 ^ z1) >> 31)) << 1);
            word |= b << (8 * q);
        }
        ((uint32_t*)g_mask)[j] = word;
    }
}

// fused: norms + scan (decoupled lookback) + U0 = fp16(norm_src * x)
__global__ void k_scan_norm_scale(const float* __restrict__ x, int n, int e) {
    __shared__ int s[1024];
    __shared__ float snorm[1024];
    __shared__ int s_prefix;
    int b = blockIdx.x, t = threadIdx.x, i = b * 1024 + t;
    int din = (i < n) ? P_DEG_IN[i] : 0;
    float ns = 0.f;
    if (i < n) {
        int a = P_DEG_OUT[i];
        ns = (a > 0) ? rsqrtf((float)a) : 0.f;
        g_norm_src[i] = ns;
        g_norm_dst[i] = (din > 0) ? rsqrtf((float)din) : 0.f;
    }
    snorm[t] = ns;
    s[t] = din;
    __syncthreads();
    for (int off = 1; off < 1024; off <<= 1) {
        int a = (t >= off) ? s[t - off] : 0;
        __syncthreads();
        s[t] += a;
        __syncthreads();
    }
    if (t == 0) {
        s_prefix = 0;
        g_blk_sum[b] = s[1023];
        __threadfence();
        *((volatile int*)&P_FLAG[b]) = 1;
    }
    __syncthreads();
    if (t < b) {
        while (*((volatile int*)&P_FLAG[t]) == 0) {}
        int v = *((volatile int*)&g_blk_sum[t]);
        atomicAdd(&s_prefix, v);
    }
    __syncthreads();
    int excl = s[t] - din + s_prefix;
    if (i < n) { g_row_ptr[i] = excl; g_fill[i] = excl; }
    if (i == 0) g_row_ptr[n] = e;

    const float4* x4 = (const float4*)x;
    int f4base = b * 1024 * 16;
#pragma unroll
    for (int q = 0; q < 16; q++) {
        int idx = f4base + q * 1024 + t;
        if (idx < n * 16) {
            float nv = snorm[(idx >> 4) - b * 1024];
            float4 v = x4[idx];
            __half2 h0 = __floats2half2_rn(v.x * nv, v.y * nv);
            __half2 h1 = __floats2half2_rn(v.z * nv, v.w * nv);
            uint2 pk;
            pk.x = *reinterpret_cast<uint32_t*>(&h0);
            pk.y = *reinterpret_cast<uint32_t*>(&h1);
            ((uint2*)g_a)[idx] = pk;
        }
    }
}

// CSR fill: 2 edges per thread (int2 loads)
__global__ void k_csr(const int* __restrict__ src, const int* __restrict__ dst,
                      int ehalf, int e) {
    int j = blockIdx.x * blockDim.x + threadIdx.x;
    if (j < ehalf) {
        int2 s2 = ((const int2*)src)[j];
        int2 t2 = ((const int2*)dst)[j];
        int p0 = atomicAdd(&g_fill[t2.x], 1);
        g_col[p0] = s2.x;
        int p1 = atomicAdd(&g_fill[t2.y], 1);
        g_col[p1] = s2.y;
    } else if (2 * j < e) {
        int p = atomicAdd(&g_fill[dst[2 * j]], 1);
        g_col[p] = src[2 * j];
    }
}

// ---------------- packed f32x2 helpers ----------------
__device__ __forceinline__ unsigned long long pk2(float x, float y) {
    unsigned long long r;
    asm("mov.b64 %0, {%1,%2};" : "=l"(r) : "f"(x), "f"(y));
    return r;
}
__device__ __forceinline__ void fma2(unsigned long long& d, unsigned long long a, unsigned long long b) {
    asm("fma.rn.f32x2 %0, %1, %2, %0;" : "+l"(d) : "l"(a), "l"(b));
}
__device__ __forceinline__ void add2(unsigned long long& d, unsigned long long v) {
    asm("add.rn.f32x2 %0, %0, %1;" : "+l"(d) : "l"(v));
}
__device__ __forceinline__ float2 upk2(unsigned long long v) {
    float2 r;
    asm("mov.b64 {%0,%1}, %2;" : "=f"(r.x), "=f"(r.y) : "l"(v));
    return r;
}

// pairwise fp16 add of two uint4s (8 half2 lanes -> 4 HADD2)
__device__ __forceinline__ uint4 hadd4(uint4 a, uint4 b) {
    uint4 r;
    __half2* pa = (__half2*)&a;
    __half2* pb = (__half2*)&b;
    __half2* pr = (__half2*)&r;
#pragma unroll
    for (int k = 0; k < 4; k++) pr[k] = __hadd2(pa[k], pb[k]);
    return r;
}

// accumulate one uint4 (= 8 fp16 cols) into 4 packed f32x2 accumulators
__device__ __forceinline__ void accq(unsigned long long* acc, uint4 v) {
    __half2* ph = (__half2*)&v;
#pragma unroll
    for (int k = 0; k < 4; k++) {
        float2 f = __half22float2(ph[k]);
        add2(acc[k], pk2(f.x, f.y));
    }
}

// ---------------- pure gather: S[v] = sum_{u in N(v)} U[u] (fp16 -> fp32) ------
// QUARTER-WARP per node: lanes 8q..8q+7 -> node 4g+q. Each lane owns 8 columns
// (uint4 = 16B; 8 lanes = full 128B row). One LDG.128 instr covers 4 node-edges;
// pairwise HADD2 halves the convert/accumulate instruction count.
__global__ void __launch_bounds__(256) k_agg(const __half* __restrict__ U, int n) {
    int gw = (blockIdx.x * blockDim.x + threadIdx.x) >> 5;
    int lane = threadIdx.x & 31;
    int q = lane >> 3, laneL = lane & 7;
    int node = 4 * gw + q;
    int s = 0, e = 0;
    if (node < n) { s = g_row_ptr[node]; e = g_row_ptr[node + 1]; }
    const uint4* T = (const uint4*)U;   // fp16 row = 8 uint4
    unsigned long long acc[4] = {0ull, 0ull, 0ull, 0ull};

    int i = s;
    for (; i + 4 <= e; i += 4) {
        int c0 = g_col[i];
        int c1 = g_col[i + 1];
        int c2 = g_col[i + 2];
        int c3 = g_col[i + 3];
        uint4 v0 = T[c0 * 8 + laneL];
        uint4 v1 = T[c1 * 8 + laneL];
        uint4 v2 = T[c2 * 8 + laneL];
        uint4 v3 = T[c3 * 8 + laneL];
        accq(acc, hadd4(v0, v1));
        accq(acc, hadd4(v2, v3));
    }
    if (i + 2 <= e) {
        uint4 v0 = T[g_col[i] * 8 + laneL];
        uint4 v1 = T[g_col[i + 1] * 8 + laneL];
        accq(acc, hadd4(v0, v1));
        i += 2;
    }
    if (i < e)
        accq(acc, T[g_col[i] * 8 + laneL]);

    if (node < n) {
        float2 f0 = upk2(acc[0]), f1 = upk2(acc[1]);
        float2 f2 = upk2(acc[2]), f3 = upk2(acc[3]);
        float4* o = (float4*)(g_s + node * 64);
        o[2 * laneL]     = make_float4(f0.x, f0.y, f1.x, f1.y);
        o[2 * laneL + 1] = make_float4(f2.x, f2.y, f3.x, f3.y);
    }
}

// ---------------- GEMM + epilogue: out = epi(norm_dst*(S@W)+b) ----------------
template <int LAYER>
__global__ void __launch_bounds__(256) k_gemm_epi(void* __restrict__ Unext,
                                                  const float* __restrict__ W,
                                                  const float* __restrict__ bias,
                                                  int pairs, int n) {
    __shared__ unsigned long long sW[64 * 32];
    __shared__ float sS[GPB * SS_STRIDE];
    int t = threadIdx.x;
    int base = blockIdx.x * GPB;
    int rid = t >> 4;
    int cid = t & 15;

    const float2* Wv = (const float2*)W;
    float2 wreg[8];
#pragma unroll
    for (int q = 0; q < 8; q++) wreg[q] = Wv[t + q * 256];

    const float4* S4 = (const float4*)g_s;
    float4 sreg[4];
#pragma unroll
    for (int q = 0; q < 4; q++) {
        int li = q * 256 + t;
        int row = li >> 4;
        int node = base + row;
        sreg[q] = (node < n) ? S4[node * 16 + (li & 15)]
                             : make_float4(0.f, 0.f, 0.f, 0.f);
    }

    unsigned char mb[4][2];
    if (LAYER != 2) {
        const unsigned char* mbase = g_mask + LAYER * pairs;
#pragma unroll
        for (int i = 0; i < 4; i++)
#pragma unroll
            for (int j = 0; j < 2; j++)
                mb[i][j] = mbase[(base + rid + 16 * i) * 32 + cid + 16 * j];
    }

#pragma unroll
    for (int q = 0; q < 8; q++) sW[t + q * 256] = pk2(wreg[q].x, wreg[q].y);
#pragma unroll
    for (int q = 0; q < 4; q++) {
        int li = q * 256 + t;
        int row = li >> 4;
        float* p = &sS[row * SS_STRIDE + (li & 15) * 4];
        p[0] = sreg[q].x; p[1] = sreg[q].y; p[2] = sreg[q].z; p[3] = sreg[q].w;
    }
    __syncthreads();

    unsigned long long acc[4][2];
#pragma unroll
    for (int i = 0; i < 4; i++)
#pragma unroll
        for (int j = 0; j < 2; j++) acc[i][j] = 0ull;

#pragma unroll 8
    for (int k = 0; k < 64; k++) {
        unsigned long long a[4], b[2];
#pragma unroll
        for (int i = 0; i < 4; i++) {
            float h = sS[(rid + 16 * i) * SS_STRIDE + k];
            a[i] = pk2(h, h);
        }
#pragma unroll
        for (int j = 0; j < 2; j++) b[j] = sW[k * 32 + cid + 16 * j];
#pragma unroll
        for (int i = 0; i < 4; i++)
#pragma unroll
            for (int j = 0; j < 2; j++) fma2(acc[i][j], a[i], b[j]);
    }

#pragma unroll
    for (int i = 0; i < 4; i++) {
        int node = base + rid + 16 * i;
        if (node < n) {
            float nd = g_norm_dst[node];
            float ns = (LAYER != 2) ? g_norm_src[node] : 0.f;
#pragma unroll
            for (int j = 0; j < 2; j++) {
                int c = cid + 16 * j;
                float2 bb = ((const float2*)bias)[c];
                float2 v = upk2(acc[i][j]);
                float ox = v.x * nd + bb.x;
                float oy = v.y * nd + bb.y;
                if (LAYER != 2) {
                    ox = fmaxf(ox, 0.f);
                    oy = fmaxf(oy, 0.f);
                    ox = (mb[i][j] & 1) ? ox * 2.f * ns : 0.f;
                    oy = (mb[i][j] & 2) ? oy * 2.f * ns : 0.f;
                    ((__half2*)Unext)[node * 32 + c] = __floats2half2_rn(ox, oy);
                } else {
                    ((float2*)Unext)[node * 32 + c] = make_float2(ox, oy);
                }
            }
        }
    }
}

// ---------------- launch ----------------
extern "C" void kernel_launch(void* const* d_in, const int* in_sizes, int n_in,
                              void* d_out, int out_size) {
    const float* x  = (const float*)d_in[0];
    const float* W0 = (const float*)d_in[1];
    const float* b0 = (const float*)d_in[2];
    const float* W1 = (const float*)d_in[3];
    const float* b1 = (const float*)d_in[4];
    const float* W2 = (const float*)d_in[5];
    const float* b2 = (const float*)d_in[6];
    const int*   src = (const int*)d_in[7];
    const int*   dst = (const int*)d_in[8];
    int n = in_sizes[0] / 64;
    int e = in_sizes[7];
    float* out = (float*)d_out;

    int nb = (n + 1023) / 1024;
    int pairs = n * 32;
    int maskWords = (2 * pairs) / 4;
    int ehalf = e / 2;

    uint32_t d0k0, d0k1, d1k0, d1k1;
    h_threefry(0u, 1u, 0u, 0u, d0k0, d0k1);
    h_threefry(0u, 1u, 0u, 1u, d1k0, d1k1);

    __half* gA; cudaGetSymbolAddress((void**)&gA, g_a);
    __half* gB; cudaGetSymbolAddress((void**)&gB, g_b);
    void* pZ; cudaGetSymbolAddress(&pZ, g_zbuf);

    int warps = (n + 3) / 4;                 // 4 nodes per warp
    int aB = (warps * 32 + 255) / 256;
    int gBk = (n + GPB - 1) / GPB;
    int dWork = ((ehalf + 1) > maskWords) ? (ehalf + 1) : maskWords;

    cudaMemsetAsync(pZ, 0, (size_t)(2 * N_MAX + NBLK_SCAN) * sizeof(int));

    k_degree_mask<<<(dWork + 255) / 256, 256>>>(src, dst, ehalf, e, pairs, maskWords,
                                                d0k0, d0k1, d1k0, d1k1);       // 0
    k_scan_norm_scale<<<nb, 1024>>>(x, n, e);                                  // 1
    k_csr<<<(ehalf + 1 + 255) / 256, 256>>>(src, dst, ehalf, e);               // 2
    k_agg<<<aB, 256>>>(gA, n);                                                 // 3 (profiled)
    k_gemm_epi<0><<<gBk, 256>>>(gB, W0, b0, pairs, n);                         // 4
    k_agg<<<aB, 256>>>(gB, n);                                                 // 5
    k_gemm_epi<1><<<gBk, 256>>>(gA, W1, b1, pairs, n);                         // 6
    k_agg<<<aB, 256>>>(gA, n);                                                 // 7
    k_gemm_epi<2><<<gBk, 256>>>(out, W2, b2, pairs, n);                        // 8
}